// round 1
// baseline (speedup 1.0000x reference)
#include <cuda_runtime.h>

#define NB 2048
#define NT 128
#define NS 256
#define NV 29
#define NE 32
#define NH 64
#define EP 17  // encoder row pitch in float4 (16 data + 1 pad) -> conflict-free both ways

// Dynamic SMEM layout (bytes):
//  encs  : NS*EP float4            = 69632
//  xb4   : 24 float4 (x = emb|ctx) =   384
//  hb4   : 16 float4 (h)           =   256
//  cpart : 128 float4              =  2048
//  buf   : 256 float (scores/attn/gates, time-shared) = 1024
//  cb    : 64 float (c state)      =   256
//  red   : 16 float                =    64
#define SMEM_BYTES (69632 + 384 + 256 + 2048 + 1024 + 256 + 64)

__global__ __launch_bounds__(256, 3) void decoder_kernel(
    const int* __restrict__ y, const float* __restrict__ h0,
    const float* __restrict__ c0, const float* __restrict__ enc,
    const float* __restrict__ emb, const float* __restrict__ Wih,
    const float* __restrict__ Whh, const float* __restrict__ bih,
    const float* __restrict__ bhh, const float* __restrict__ fcW,
    const float* __restrict__ fcb, float* __restrict__ out)
{
    const int b = blockIdx.x;
    const int tid = threadIdx.x;
    const int lane = tid & 31;
    const int wrp = tid >> 5;

    extern __shared__ float4 sm4[];
    float4* encs = sm4;                     // [NS*EP]
    float4* xb4  = encs + NS * EP;          // [24]  x = [emb(8 f4) | context(16 f4)]
    float4* hb4  = xb4 + 24;                // [16]
    float4* cpart= hb4 + 16;                // [128]
    float*  buf  = (float*)(cpart + 128);   // [256]
    float*  cb   = buf + 256;               // [64]
    float*  red  = cb + 64;                 // [16]
    float*  xb   = (float*)xb4;
    float*  hb   = (float*)hb4;

    // ---- one-time: stage this batch element's encoder slice into SMEM ----
    const float4* eg = (const float4*)(enc + (size_t)b * NS * NH);
    #pragma unroll 4
    for (int g = tid; g < NS * 16; g += 256)
        encs[(g >> 4) * EP + (g & 15)] = eg[g];

    if (tid < NH) { hb[tid] = h0[b * NH + tid]; cb[tid] = c0[b * NH + tid]; }
    __syncthreads();

    for (int t = 0; t < NT; t++) {
        const int yv = y[b * NT + t];

        // ---- attention scores: thread s = tid, dot(enc[s,:], h) over 64 ----
        float sc = 0.f;
        {
            const float4* er = encs + tid * EP;
            #pragma unroll
            for (int k = 0; k < 16; k++) {
                float4 e = er[k], hv = hb4[k];
                sc = fmaf(e.x, hv.x, fmaf(e.y, hv.y, fmaf(e.z, hv.z, fmaf(e.w, hv.w, sc))));
            }
        }

        // ---- softmax: max ----
        float m = sc;
        #pragma unroll
        for (int o = 16; o; o >>= 1) m = fmaxf(m, __shfl_xor_sync(~0u, m, o));
        if (lane == 0) red[wrp] = m;
        __syncthreads();
        if (tid == 0) {
            float mm = red[0];
            #pragma unroll
            for (int i = 1; i < 8; i++) mm = fmaxf(mm, red[i]);
            red[8] = mm;
        }
        __syncthreads();

        // ---- softmax: exp + sum (unnormalized weights kept in buf) ----
        float p = __expf(sc - red[8]);
        buf[tid] = p;
        float sm_ = p;
        #pragma unroll
        for (int o = 16; o; o >>= 1) sm_ += __shfl_xor_sync(~0u, sm_, o);
        if (lane == 0) red[wrp] = sm_;
        // embedding lookup overlapped here (xb free: prev logits readers passed a barrier)
        if (tid < NE) xb[tid] = emb[yv * NE + tid];
        __syncthreads();
        if (tid == 0) {
            float s2 = red[0];
            #pragma unroll
            for (int i = 1; i < 8; i++) s2 += red[i];
            red[9] = 1.f / s2;
        }

        // ---- context partials: 128 threads, (k4 = tid&15, s-group = tid>>4 of 32) ----
        if (tid < 128) {
            const int k4 = tid & 15, sg = tid >> 4;
            float4 a = make_float4(0.f, 0.f, 0.f, 0.f);
            const float* at = buf + sg * 32;
            const float4* ec = encs + (sg * 32) * EP + k4;
            #pragma unroll 8
            for (int i = 0; i < 32; i++) {
                const float w = at[i];
                const float4 e = ec[i * EP];
                a.x = fmaf(w, e.x, a.x); a.y = fmaf(w, e.y, a.y);
                a.z = fmaf(w, e.z, a.z); a.w = fmaf(w, e.w, a.w);
            }
            cpart[tid] = a;
        }
        __syncthreads();
        if (tid < 16) {
            float4 a = cpart[tid];
            #pragma unroll
            for (int g = 1; g < 8; g++) {
                const float4 v = cpart[g * 16 + tid];
                a.x += v.x; a.y += v.y; a.z += v.z; a.w += v.w;
            }
            const float inv = red[9];
            a.x *= inv; a.y *= inv; a.z *= inv; a.w *= inv;
            xb4[8 + tid] = a;   // context -> x[32:96]
        }
        __syncthreads();

        // ---- gates: thread j = tid owns gate row j ----
        {
            float g = bih[tid] + bhh[tid];
            const float4* wi = (const float4*)Wih + tid * 24;
            #pragma unroll
            for (int k = 0; k < 24; k++) {
                const float4 w = wi[k], xv = xb4[k];
                g = fmaf(w.x, xv.x, fmaf(w.y, xv.y, fmaf(w.z, xv.z, fmaf(w.w, xv.w, g))));
            }
            const float4* wh = (const float4*)Whh + tid * 16;
            #pragma unroll
            for (int k = 0; k < 16; k++) {
                const float4 w = wh[k], hv = hb4[k];
                g = fmaf(w.x, hv.x, fmaf(w.y, hv.y, fmaf(w.z, hv.z, fmaf(w.w, hv.w, g))));
            }
            buf[tid] = g;  // buf now time-shared as gates
        }
        __syncthreads();

        // ---- LSTM elementwise update (gate order i,f,g,o) ----
        if (tid < NH) {
            const float ig = buf[tid], fg = buf[NH + tid];
            const float gg = buf[2 * NH + tid], og = buf[3 * NH + tid];
            const float si = 1.f / (1.f + __expf(-ig));
            const float sf = 1.f / (1.f + __expf(-fg));
            const float so = 1.f / (1.f + __expf(-og));
            const float cn = fmaf(sf, cb[tid], si * tanhf(gg));
            const float hn = so * tanhf(cn);
            cb[tid] = cn; hb[tid] = hn;
        }
        __syncthreads();

        // ---- logits: 8 threads per vocab row, shfl-reduce width 8 ----
        {
            const int v = tid >> 3, l = tid & 7;
            float acc = 0.f;
            if (v < NV) {
                const float4* fw = (const float4*)fcW + v * 32;
                #pragma unroll
                for (int k = l; k < 32; k += 8) {
                    const float4 w = fw[k];
                    const float4 cv = (k < 16) ? hb4[k] : xb4[k - 8]; // [h | context]
                    acc = fmaf(w.x, cv.x, fmaf(w.y, cv.y, fmaf(w.z, cv.z, fmaf(w.w, cv.w, acc))));
                }
            }
            #pragma unroll
            for (int o = 4; o; o >>= 1) acc += __shfl_down_sync(~0u, acc, o, 8);
            if (v < NV && l == 0)
                out[((size_t)b * NT + t) * NV + v] = acc + fcb[v];
        }
        // next iteration's softmax barriers order logits reads vs. xb/buf rewrites
    }
}

extern "C" void kernel_launch(void* const* d_in, const int* in_sizes, int n_in,
                              void* d_out, int out_size) {
    const int*   y    = (const int*)  d_in[0];
    const float* h0   = (const float*)d_in[1];
    const float* c0   = (const float*)d_in[2];
    const float* enc  = (const float*)d_in[3];
    const float* emb  = (const float*)d_in[4];
    const float* Wih  = (const float*)d_in[5];
    const float* Whh  = (const float*)d_in[6];
    const float* bih  = (const float*)d_in[7];
    const float* bhh  = (const float*)d_in[8];
    const float* fcW  = (const float*)d_in[9];
    const float* fcb  = (const float*)d_in[10];
    float* out = (float*)d_out;

    cudaFuncSetAttribute(decoder_kernel,
                         cudaFuncAttributeMaxDynamicSharedMemorySize, SMEM_BYTES);
    decoder_kernel<<<NB, 256, SMEM_BYTES>>>(y, h0, c0, enc, emb, Wih, Whh,
                                            bih, bhh, fcW, fcb, out);
}

// round 2
// speedup vs baseline: 5.4165x; 5.4165x over previous
#include <cuda_runtime.h>

#define NB 2048
#define NT 128
#define NS 256
#define NV 29
#define NE 32
#define NH 64
#define EP 17      // encoder row pitch in float4 (16 data + 1 pad)
#define G  2       // batch elements per CTA
#define THREADS 512
#define FCP 33     // fcW row pitch in float4 (32 data + 1 pad)

// SMEM (float4 units): encs 2*256*17=8704 | xh 2*40=80 | cpart 2*256=512 | fcw 29*33=957
// then floats: buf 512 | cb 128 | reds 16 | inv 2 | fcbs 32
#define SMEM_BYTES ((8704 + 80 + 512 + 957) * 16 + (512 + 128 + 16 + 2 + 32) * 4)

__global__ __launch_bounds__(THREADS, 1) void decoder_kernel(
    const int* __restrict__ y, const float* __restrict__ h0,
    const float* __restrict__ c0, const float* __restrict__ enc,
    const float* __restrict__ emb, const float* __restrict__ Wih,
    const float* __restrict__ Whh, const float* __restrict__ bih,
    const float* __restrict__ bhh, const float* __restrict__ fcW,
    const float* __restrict__ fcb, float* __restrict__ out)
{
    const int tid  = threadIdx.x;
    const int b0   = blockIdx.x * G;
    const int g    = tid >> 8;        // batch element within CTA
    const int s    = tid & 255;       // score index within group
    const int lane = tid & 31;
    const int wrp  = tid >> 5;        // 0..15

    extern __shared__ float4 sm4[];
    float4* encs  = sm4;                       // [G][NS][EP]
    float4* xh4   = encs + G * NS * EP;        // [G][40]: emb(0..7) ctx(8..23) h(24..39)
    float4* cpart = xh4 + G * 40;              // [G][16][16]
    float4* fcw4  = cpart + G * 256;           // [NV][FCP]
    float*  buf   = (float*)(fcw4 + NV * FCP); // [G][256] scores->gates (time-shared)
    float*  cb    = buf + G * 256;             // [G][64]
    float*  reds  = cb + G * 64;               // [16]
    float*  inv   = reds + 16;                 // [G]
    float*  fcbs  = inv + G;                   // [NV]
    float*  xh    = (float*)xh4;

    // ---- one-time staging ----
    for (int i = tid; i < G * NS * 16; i += THREADS) {
        const int gg = i >> 12, r = (i >> 4) & 255, k = i & 15;
        encs[(gg * NS + r) * EP + k] =
            ((const float4*)(enc + (size_t)(b0 + gg) * NS * NH))[r * 16 + k];
    }
    for (int i = tid; i < NV * 32; i += THREADS)
        fcw4[(i >> 5) * FCP + (i & 31)] = ((const float4*)fcW)[i];
    if (tid < NV) fcbs[tid] = fcb[tid];
    if (tid < G * NH) {
        const int gg = tid >> 6, j = tid & 63;
        xh[gg * 160 + 96 + j] = h0[(b0 + gg) * NH + j];
        cb[gg * 64 + j]       = c0[(b0 + gg) * NH + j];
    }

    // ---- weights -> registers: thread owns half of combined row [Wih|Whh] ----
    const int row  = tid >> 1;
    const int half = tid & 1;
    float4 w[20];
    {
        const float4* wi = (const float4*)Wih + row * 24;
        const float4* wh = (const float4*)Whh + row * 16;
        if (half == 0) {
            #pragma unroll
            for (int j = 0; j < 20; j++) w[j] = wi[j];
        } else {
            #pragma unroll
            for (int j = 0; j < 4; j++)  w[j] = wi[20 + j];
            #pragma unroll
            for (int j = 0; j < 16; j++) w[4 + j] = wh[j];
        }
    }
    const float bsum = bih[row] + bhh[row];
    __syncthreads();

    for (int t = 0; t < NT; t++) {
        // ---- P1: scores + exp + warp partial sums (no max pass needed in fp32) ----
        {
            const float4* er  = encs + (g * NS + s) * EP;
            const float4* hv4 = xh4 + g * 40 + 24;
            float sc = 0.f;
            #pragma unroll
            for (int k = 0; k < 16; k++) {
                const float4 e = er[k], hv = hv4[k];
                sc = fmaf(e.x, hv.x, fmaf(e.y, hv.y, fmaf(e.z, hv.z, fmaf(e.w, hv.w, sc))));
            }
            const float p = __expf(sc);
            buf[g * 256 + s] = p;
            float sum = p;
            #pragma unroll
            for (int o = 16; o; o >>= 1) sum += __shfl_xor_sync(~0u, sum, o);
            if (lane == 0) reds[wrp] = sum;
        }
        __syncthreads();  // B1

        // ---- P2 (2 threads): 1/sum, overlapped with P3 ----
        if (s == 0) {
            float t0 = 0.f;
            #pragma unroll
            for (int i = 0; i < 8; i++) t0 += reds[g * 8 + i];
            inv[g] = 1.f / t0;
        }
        // ---- P3: context partials (all 512 threads) ----
        {
            const int k4 = tid & 15, sg = (tid >> 4) & 15;
            const float*  at = buf + g * 256 + sg * 16;
            const float4* ec = encs + (g * NS + sg * 16) * EP + k4;
            float4 a = make_float4(0.f, 0.f, 0.f, 0.f);
            #pragma unroll
            for (int i = 0; i < 16; i++) {
                const float wa = at[i];
                const float4 e = ec[i * EP];
                a.x = fmaf(wa, e.x, a.x); a.y = fmaf(wa, e.y, a.y);
                a.z = fmaf(wa, e.z, a.z); a.w = fmaf(wa, e.w, a.w);
            }
            cpart[(g * 16 + sg) * 16 + k4] = a;
        }
        // ---- P3b: embedding fetch (8 threads per group; xh[0..7] not read until gates) ----
        if (s >= 64 && s < 72) {
            const int k  = tid & 7;
            const int yv = y[(b0 + g) * NT + t];
            xh4[g * 40 + k] = ((const float4*)emb)[yv * 8 + k];
        }
        __syncthreads();  // B2

        // ---- P4: context reduce + normalize -> xh[g][8..23] ----
        if (tid < 32) {
            const int gg = tid >> 4, k4 = tid & 15;
            const float4* cp = cpart + gg * 256 + k4;
            float4 a = cp[0];
            #pragma unroll
            for (int sg = 1; sg < 16; sg++) {
                const float4 v = cp[sg * 16];
                a.x += v.x; a.y += v.y; a.z += v.z; a.w += v.w;
            }
            const float iv = inv[gg];
            a.x *= iv; a.y *= iv; a.z *= iv; a.w *= iv;
            xh4[gg * 40 + 8 + k4] = a;
        }
        __syncthreads();  // B3

        // ---- P5: gates, weights from registers, both batches ----
        {
            float acc0 = 0.f, acc1 = 0.f;
            const float4* x0 = xh4 + half * 20;
            const float4* x1 = xh4 + 40 + half * 20;
            #pragma unroll
            for (int j = 0; j < 20; j++) {
                const float4 xv = x0[j];
                acc0 = fmaf(w[j].x, xv.x, fmaf(w[j].y, xv.y, fmaf(w[j].z, xv.z, fmaf(w[j].w, xv.w, acc0))));
            }
            #pragma unroll
            for (int j = 0; j < 20; j++) {
                const float4 xv = x1[j];
                acc1 = fmaf(w[j].x, xv.x, fmaf(w[j].y, xv.y, fmaf(w[j].z, xv.z, fmaf(w[j].w, xv.w, acc1))));
            }
            acc0 += __shfl_xor_sync(~0u, acc0, 1);
            acc1 += __shfl_xor_sync(~0u, acc1, 1);
            if (half == 0) {
                buf[row]       = acc0 + bsum;
                buf[256 + row] = acc1 + bsum;
            }
        }
        __syncthreads();  // B4

        // ---- P6: LSTM elementwise (gate order i,f,g,o) ----
        if (tid < G * NH) {
            const int gg = tid >> 6, j = tid & 63;
            const float* gb = buf + gg * 256;
            const float ig = gb[j], fg = gb[64 + j], ggt = gb[128 + j], og = gb[192 + j];
            const float si = 1.f / (1.f + __expf(-ig));
            const float sf = 1.f / (1.f + __expf(-fg));
            const float so = 1.f / (1.f + __expf(-og));
            const float cn = fmaf(sf, cb[gg * 64 + j], si * tanhf(ggt));
            cb[gg * 64 + j] = cn;
            xh[gg * 160 + 96 + j] = so * tanhf(cn);
        }
        __syncthreads();  // B5

        // ---- P7: logits (combined = [h | ctx]), 8 threads per vocab row ----
        {
            const int v = s >> 3, l = tid & 7;
            float acc = 0.f;
            if (v < NV) {
                const float4* fr = fcw4 + v * FCP + l;
                const float4 w0 = fr[0],  a0 = xh4[g * 40 + 24 + l];
                const float4 w1 = fr[8],  a1 = xh4[g * 40 + 32 + l];
                const float4 w2 = fr[16], a2 = xh4[g * 40 + 8 + l];
                const float4 w3 = fr[24], a3 = xh4[g * 40 + 16 + l];
                acc = fmaf(w0.x, a0.x, fmaf(w0.y, a0.y, fmaf(w0.z, a0.z, w0.w * a0.w)));
                acc = fmaf(w1.x, a1.x, fmaf(w1.y, a1.y, fmaf(w1.z, a1.z, fmaf(w1.w, a1.w, acc))));
                acc = fmaf(w2.x, a2.x, fmaf(w2.y, a2.y, fmaf(w2.z, a2.z, fmaf(w2.w, a2.w, acc))));
                acc = fmaf(w3.x, a3.x, fmaf(w3.y, a3.y, fmaf(w3.z, a3.z, fmaf(w3.w, a3.w, acc))));
            }
            acc += __shfl_down_sync(~0u, acc, 4, 8);
            acc += __shfl_down_sync(~0u, acc, 2, 8);
            acc += __shfl_down_sync(~0u, acc, 1, 8);
            if (v < NV && l == 0)
                out[((size_t)(b0 + g) * NT + t) * NV + v] = acc + fcbs[v];
        }
        // no barrier needed: next-iter writes to xh/buf are ordered behind B1/B2
    }
}

extern "C" void kernel_launch(void* const* d_in, const int* in_sizes, int n_in,
                              void* d_out, int out_size) {
    const int*   y    = (const int*)  d_in[0];
    const float* h0   = (const float*)d_in[1];
    const float* c0   = (const float*)d_in[2];
    const float* enc  = (const float*)d_in[3];
    const float* emb  = (const float*)d_in[4];
    const float* Wih  = (const float*)d_in[5];
    const float* Whh  = (const float*)d_in[6];
    const float* bih  = (const float*)d_in[7];
    const float* bhh  = (const float*)d_in[8];
    const float* fcW  = (const float*)d_in[9];
    const float* fcb  = (const float*)d_in[10];
    float* out = (float*)d_out;

    cudaFuncSetAttribute(decoder_kernel,
                         cudaFuncAttributeMaxDynamicSharedMemorySize, SMEM_BYTES);
    decoder_kernel<<<NB / G, THREADS, SMEM_BYTES>>>(y, h0, c0, enc, emb, Wih, Whh,
                                                    bih, bhh, fcW, fcb, out);
}

// round 3
// speedup vs baseline: 5.4824x; 1.0122x over previous
#include <cuda_runtime.h>

#define NB 2048
#define NT 128
#define NS 256
#define NV 29
#define NE 32
#define NH 64
#define EP 17      // encoder row pitch in float4 (16 data + 1 pad)
#define G  2       // batch elements per CTA
#define THREADS 512
#define FCP 33     // fcW row pitch in float4

// SMEM: encs 8704 f4 | xh 80 f4 | cpart 256 f4 | fcw 957 f4
//       buf 512 f | buf2 1024 f | cb 128 f | reds 16 f | fcbs 32 f
#define SMEM_BYTES ((8704 + 80 + 256 + 957) * 16 + (512 + 1024 + 128 + 16 + 32) * 4)

__device__ __forceinline__ float2 ffma2(float2 a, float2 b, float2 c) {
    union U { float2 f; unsigned long long u; };
    U ua, ub, uc, d;
    ua.f = a; ub.f = b; uc.f = c;
    asm("fma.rn.f32x2 %0, %1, %2, %3;" : "=l"(d.u) : "l"(ua.u), "l"(ub.u), "l"(uc.u));
    return d.f;
}
__device__ __forceinline__ float fast_sigmoid(float x) {
    return __frcp_rn(1.f + __expf(-x));
}
__device__ __forceinline__ float fast_tanh(float x) {
    // 1 - 2/(e^{2x}+1); exact at +/-inf via expf saturation
    return fmaf(-2.f, __frcp_rn(__expf(2.f * x) + 1.f), 1.f);
}

__global__ __launch_bounds__(THREADS, 1) void decoder_kernel(
    const int* __restrict__ y, const float* __restrict__ h0,
    const float* __restrict__ c0, const float* __restrict__ enc,
    const float* __restrict__ emb, const float* __restrict__ Wih,
    const float* __restrict__ Whh, const float* __restrict__ bih,
    const float* __restrict__ bhh, const float* __restrict__ fcW,
    const float* __restrict__ fcb, float* __restrict__ out)
{
    const int tid  = threadIdx.x;
    const int b0   = blockIdx.x * G;
    const int g    = tid >> 8;        // group for P1/P3/P7
    const int s    = tid & 255;
    const int lane = tid & 31;
    const int wrp  = tid >> 5;

    extern __shared__ float4 sm4[];
    float4* encs  = sm4;                       // [G][NS][EP]
    float4* xh4   = encs + G * NS * EP;        // [G][40]: emb(0..7) ctx(8..23) h(24..39)
    float4* cpart = xh4 + G * 40;              // [G][8][16]
    float4* fcw4  = cpart + G * 8 * 16;        // [NV][FCP]
    float*  buf   = (float*)(fcw4 + NV * FCP); // [G][256] exp(scores)
    float*  buf2  = buf + G * 256;             // [2][G][256] gate partials
    float*  cb    = buf2 + 2 * G * 256;        // [G][64]
    float*  reds  = cb + G * 64;               // [16]
    float*  fcbs  = reds + 16;                 // [NV]
    float*  xh    = (float*)xh4;

    // ---- one-time staging ----
    for (int i = tid; i < G * NS * 16; i += THREADS) {
        const int gg = i >> 12, r = (i >> 4) & 255, k = i & 15;
        encs[(gg * NS + r) * EP + k] =
            ((const float4*)(enc + (size_t)(b0 + gg) * NS * NH))[r * 16 + k];
    }
    for (int i = tid; i < NV * 32; i += THREADS)
        fcw4[(i >> 5) * FCP + (i & 31)] = ((const float4*)fcW)[i];
    if (tid < NV) fcbs[tid] = fcb[tid];
    if (tid < G * NH) {
        const int gg = tid >> 6, j = tid & 63;
        xh[gg * 160 + 96 + j] = h0[(b0 + gg) * NH + j];
        cb[gg * 64 + j]       = c0[(b0 + gg) * NH + j];
    }

    // ---- weights -> registers: (row = tid&255, half = tid>>8) ----
    const int row  = tid & 255;
    const int half = tid >> 8;
    float4 w[20];
    {
        const float4* wi = (const float4*)Wih + row * 24;
        const float4* wh = (const float4*)Whh + row * 16;
        if (half == 0) {
            #pragma unroll
            for (int j = 0; j < 20; j++) w[j] = wi[j];
        } else {
            #pragma unroll
            for (int j = 0; j < 4; j++)  w[j] = wi[20 + j];
            #pragma unroll
            for (int j = 0; j < 16; j++) w[4 + j] = wh[j];
        }
    }
    const float bsum = (half == 0) ? (bih[row] + bhh[row]) : 0.f;
    __syncthreads();

    for (int t = 0; t < NT; t++) {
        // ---- P1: scores + exp + warp partial sums (packed f32x2) ----
        {
            const float4* er  = encs + (g * NS + s) * EP;
            const float4* hv4 = xh4 + g * 40 + 24;
            float2 a0 = make_float2(0.f, 0.f), a1 = make_float2(0.f, 0.f);
            #pragma unroll
            for (int k = 0; k < 16; k++) {
                const float4 e = er[k], hv = hv4[k];
                a0 = ffma2(make_float2(e.x, e.y), make_float2(hv.x, hv.y), a0);
                a1 = ffma2(make_float2(e.z, e.w), make_float2(hv.z, hv.w), a1);
            }
            const float p = __expf(a0.x + a0.y + a1.x + a1.y);
            buf[g * 256 + s] = p;
            float sum = p;
            #pragma unroll
            for (int o = 16; o; o >>= 1) sum += __shfl_xor_sync(~0u, sum, o);
            if (lane == 0) reds[wrp] = sum;
        }
        __syncthreads();  // B1

        // ---- P3: context partials (packed), pre-reduced by shfl_xor(16) ----
        {
            const int k4 = tid & 15, sg = (tid >> 4) & 15;
            const float*  at = buf + g * 256 + sg * 16;
            const float4* ec = encs + (g * NS + sg * 16) * EP + k4;
            float2 aXY = make_float2(0.f, 0.f), aZW = make_float2(0.f, 0.f);
            #pragma unroll
            for (int i = 0; i < 16; i++) {
                const float wa = at[i];
                const float4 e = ec[i * EP];
                aXY = ffma2(make_float2(e.x, e.y), make_float2(wa, wa), aXY);
                aZW = ffma2(make_float2(e.z, e.w), make_float2(wa, wa), aZW);
            }
            aXY.x += __shfl_xor_sync(~0u, aXY.x, 16);
            aXY.y += __shfl_xor_sync(~0u, aXY.y, 16);
            aZW.x += __shfl_xor_sync(~0u, aZW.x, 16);
            aZW.y += __shfl_xor_sync(~0u, aZW.y, 16);
            if ((sg & 1) == 0)
                cpart[(g * 8 + (sg >> 1)) * 16 + k4] =
                    make_float4(aXY.x, aXY.y, aZW.x, aZW.y);
        }
        // ---- P3b: embedding fetch (8 threads per group) ----
        if (s >= 64 && s < 72) {
            const int k  = tid & 7;
            const int yv = y[(b0 + g) * NT + t];
            xh4[g * 40 + k] = ((const float4*)emb)[yv * 8 + k];
        }
        __syncthreads();  // B2

        // ---- P4: context reduce + normalize (inv folded in) ----
        if (tid < 32) {
            const int gg = tid >> 4, k4 = tid & 15;
            float ssum = reds[gg * 8];
            #pragma unroll
            for (int i = 1; i < 8; i++) ssum += reds[gg * 8 + i];
            const float iv = __frcp_rn(ssum);
            const float4* cp = cpart + gg * 8 * 16 + k4;
            float4 a = cp[0];
            #pragma unroll
            for (int sgp = 1; sgp < 8; sgp++) {
                const float4 v = cp[sgp * 16];
                a.x += v.x; a.y += v.y; a.z += v.z; a.w += v.w;
            }
            xh4[gg * 40 + 8 + k4] = make_float4(a.x * iv, a.y * iv, a.z * iv, a.w * iv);
        }
        __syncthreads();  // B3

        // ---- P5: gate partials; all xh reads uniform per warp (broadcast) ----
        {
            const float4* x0 = xh4 + half * 20;        // group 0
            const float4* x1 = xh4 + 40 + half * 20;   // group 1
            float2 p0 = make_float2(0.f, 0.f), q0 = make_float2(0.f, 0.f);
            float2 p1 = make_float2(0.f, 0.f), q1 = make_float2(0.f, 0.f);
            #pragma unroll
            for (int j = 0; j < 20; j++) {
                const float4 wv = w[j];
                const float4 xa = x0[j];
                p0 = ffma2(make_float2(wv.x, wv.y), make_float2(xa.x, xa.y), p0);
                q0 = ffma2(make_float2(wv.z, wv.w), make_float2(xa.z, xa.w), q0);
                const float4 xb = x1[j];
                p1 = ffma2(make_float2(wv.x, wv.y), make_float2(xb.x, xb.y), p1);
                q1 = ffma2(make_float2(wv.z, wv.w), make_float2(xb.z, xb.w), q1);
            }
            buf2[half * 512 + row]       = p0.x + p0.y + q0.x + q0.y + bsum;
            buf2[half * 512 + 256 + row] = p1.x + p1.y + q1.x + q1.y + bsum;
        }
        __syncthreads();  // B4

        // ---- P6: combine halves + LSTM elementwise (i,f,g,o) ----
        if (tid < G * NH) {
            const int gg = tid >> 6, j = tid & 63;
            const float* g0 = buf2 + gg * 256;
            const float* g1 = buf2 + 512 + gg * 256;
            const float ig = g0[j]       + g1[j];
            const float fg = g0[64 + j]  + g1[64 + j];
            const float gt = g0[128 + j] + g1[128 + j];
            const float og = g0[192 + j] + g1[192 + j];
            const float cn = fmaf(fast_sigmoid(fg), cb[gg * 64 + j],
                                  fast_sigmoid(ig) * fast_tanh(gt));
            cb[gg * 64 + j] = cn;
            xh[gg * 160 + 96 + j] = fast_sigmoid(og) * fast_tanh(cn);
        }
        __syncthreads();  // B5

        // ---- P7: logits (packed), 8 threads per vocab row ----
        {
            const int v = s >> 3, l = tid & 7;
            float acc = 0.f;
            if (v < NV) {
                const float4* fr = fcw4 + v * FCP + l;
                float2 a2 = make_float2(0.f, 0.f);
                const float4 w0 = fr[0],  c0v = xh4[g * 40 + 24 + l];  // h lo
                const float4 w1 = fr[8],  c1v = xh4[g * 40 + 32 + l];  // h hi
                const float4 w2 = fr[16], c2v = xh4[g * 40 + 8 + l];   // ctx lo
                const float4 w3 = fr[24], c3v = xh4[g * 40 + 16 + l];  // ctx hi
                a2 = ffma2(make_float2(w0.x, w0.y), make_float2(c0v.x, c0v.y), a2);
                a2 = ffma2(make_float2(w0.z, w0.w), make_float2(c0v.z, c0v.w), a2);
                a2 = ffma2(make_float2(w1.x, w1.y), make_float2(c1v.x, c1v.y), a2);
                a2 = ffma2(make_float2(w1.z, w1.w), make_float2(c1v.z, c1v.w), a2);
                a2 = ffma2(make_float2(w2.x, w2.y), make_float2(c2v.x, c2v.y), a2);
                a2 = ffma2(make_float2(w2.z, w2.w), make_float2(c2v.z, c2v.w), a2);
                a2 = ffma2(make_float2(w3.x, w3.y), make_float2(c3v.x, c3v.y), a2);
                a2 = ffma2(make_float2(w3.z, w3.w), make_float2(c3v.z, c3v.w), a2);
                acc = a2.x + a2.y;
            }
            acc += __shfl_down_sync(~0u, acc, 4, 8);
            acc += __shfl_down_sync(~0u, acc, 2, 8);
            acc += __shfl_down_sync(~0u, acc, 1, 8);
            if (v < NV && l == 0)
                out[((size_t)(b0 + g) * NT + t) * NV + v] = acc + fcbs[v];
        }
        // no trailing barrier: next-iter writes ordered behind B1/B2
    }
}

extern "C" void kernel_launch(void* const* d_in, const int* in_sizes, int n_in,
                              void* d_out, int out_size) {
    const int*   y    = (const int*)  d_in[0];
    const float* h0   = (const float*)d_in[1];
    const float* c0   = (const float*)d_in[2];
    const float* enc  = (const float*)d_in[3];
    const float* emb  = (const float*)d_in[4];
    const float* Wih  = (const float*)d_in[5];
    const float* Whh  = (const float*)d_in[6];
    const float* bih  = (const float*)d_in[7];
    const float* bhh  = (const float*)d_in[8];
    const float* fcW  = (const float*)d_in[9];
    const float* fcb  = (const float*)d_in[10];
    float* out = (float*)d_out;

    cudaFuncSetAttribute(decoder_kernel,
                         cudaFuncAttributeMaxDynamicSharedMemorySize, SMEM_BYTES);
    decoder_kernel<<<NB / G, THREADS, SMEM_BYTES>>>(y, h0, c0, enc, emb, Wih, Whh,
                                                    bih, bhh, fcW, fcb, out);
}